// round 6
// baseline (speedup 1.0000x reference)
#include <cuda_runtime.h>

#define NROWS 8192
#define NDIM  512
#define ND4   128      // NDIM/4
#define NTOP  100
#define NBLK  128
#define NTHR  512

__device__ float4 g_spart[NBLK][ND4];
__device__ unsigned int g_key[NROWS];
__device__ int    g_rank2row[NTOP];
__device__ volatile unsigned int g_bar[4];   // [0..2] phase barriers, [3] done ctr

__device__ __forceinline__ void gridbar(int i) {
    __threadfence();
    __syncthreads();
    if (threadIdx.x == 0) {
        atomicAdd((unsigned int*)&g_bar[i], 1u);
        while (g_bar[i] < NBLK) __nanosleep(32);
    }
    __syncthreads();
}

__global__ void __launch_bounds__(NTHR, 1) kFused(const float4* __restrict__ x4,
                                                  float* __restrict__ out,
                                                  float4* __restrict__ out4,
                                                  int out_size) {
    __shared__ union {
        float4 sacc[8][ND4];                                     // 16 KB (P1)
        struct { float4 sred[4][ND4]; float4 s4[ND4]; } p3;      // 10 KB
        struct { int hist[256]; unsigned int ckey[256];
                 int cidx[256]; } p4;                            // 3 KB
    } sh;
    __shared__ unsigned int sh_prefix;
    __shared__ int sh_needed, sh_ncand;

    const int t    = threadIdx.x;
    const int wid  = t >> 5;          // 0..15
    const int lane = t & 31;

    // ===== P1: load 4 rows/thread into REGISTERS (kept live through P3),
    //           per-row 1/||x||, column-sum of unit rows =====
    float4 v[4][4];
    float  rinvs[4];
    {
        // front-batch all 16 LDG.128 for max MLP
        #pragma unroll
        for (int r = 0; r < 4; ++r) {
            int row = blockIdx.x * 64 + wid * 4 + r;
            const float4* xr = x4 + (size_t)row * ND4;
            #pragma unroll
            for (int k = 0; k < 4; ++k) v[r][k] = xr[lane + 32 * k];
        }

        float4 acc[4];
        #pragma unroll
        for (int k = 0; k < 4; ++k) acc[k] = make_float4(0.f, 0.f, 0.f, 0.f);

        #pragma unroll
        for (int r = 0; r < 4; ++r) {
            float sq = 0.f;
            #pragma unroll
            for (int k = 0; k < 4; ++k)
                sq += v[r][k].x*v[r][k].x + v[r][k].y*v[r][k].y
                    + v[r][k].z*v[r][k].z + v[r][k].w*v[r][k].w;
            #pragma unroll
            for (int o = 16; o; o >>= 1) sq += __shfl_xor_sync(0xffffffffu, sq, o);

            float rinv = rsqrtf(sq);
            rinv = rinv * (1.5f - 0.5f * sq * rinv * rinv);   // Newton refine
            rinvs[r] = rinv;

            #pragma unroll
            for (int k = 0; k < 4; ++k) {
                acc[k].x = fmaf(v[r][k].x, rinv, acc[k].x);
                acc[k].y = fmaf(v[r][k].y, rinv, acc[k].y);
                acc[k].z = fmaf(v[r][k].z, rinv, acc[k].z);
                acc[k].w = fmaf(v[r][k].w, rinv, acc[k].w);
            }
        }
        // 16 warps -> 8 smem buffers -> 1
        if (wid >= 8) {
            #pragma unroll
            for (int k = 0; k < 4; ++k) sh.sacc[wid - 8][lane + 32 * k] = acc[k];
        }
        __syncthreads();
        if (wid < 8) {
            #pragma unroll
            for (int k = 0; k < 4; ++k) {
                float4 o = sh.sacc[wid][lane + 32 * k];
                acc[k].x += o.x; acc[k].y += o.y; acc[k].z += o.z; acc[k].w += o.w;
                sh.sacc[wid][lane + 32 * k] = acc[k];
            }
        }
        __syncthreads();
        if (t < ND4) {
            float4 s = sh.sacc[0][t];
            #pragma unroll
            for (int w = 1; w < 8; ++w) {
                float4 u = sh.sacc[w][t];
                s.x += u.x; s.y += u.y; s.z += u.z; s.w += u.w;
            }
            g_spart[blockIdx.x][t] = s;
        }
    }
    gridbar(0);

    // ===== P3: each block reduces s itself (L2), then REGISTER dots =====
    {
        int d = t & (ND4 - 1);
        int q = t >> 7;                 // 0..3, 32 partials each
        float4 s = make_float4(0.f, 0.f, 0.f, 0.f);
        #pragma unroll 4
        for (int p = q * 32; p < (q + 1) * 32; ++p) {
            float4 u = g_spart[p][d];
            s.x += u.x; s.y += u.y; s.z += u.z; s.w += u.w;
        }
        sh.p3.sred[q][d] = s;
        __syncthreads();
        if (t < ND4) {
            float4 a = sh.p3.sred[0][t];
            #pragma unroll
            for (int w = 1; w < 4; ++w) {
                float4 u = sh.p3.sred[w][t];
                a.x += u.x; a.y += u.y; a.z += u.z; a.w += u.w;
            }
            sh.p3.s4[t] = a;
        }
        __syncthreads();

        float4 sv[4];
        #pragma unroll
        for (int k = 0; k < 4; ++k) sv[k] = sh.p3.s4[lane + 32 * k];

        #pragma unroll
        for (int r = 0; r < 4; ++r) {
            float dot = 0.f;
            #pragma unroll
            for (int k = 0; k < 4; ++k) {
                dot = fmaf(v[r][k].x, sv[k].x, dot);
                dot = fmaf(v[r][k].y, sv[k].y, dot);
                dot = fmaf(v[r][k].z, sv[k].z, dot);
                dot = fmaf(v[r][k].w, sv[k].w, dot);
            }
            #pragma unroll
            for (int o = 16; o; o >>= 1) dot += __shfl_down_sync(0xffffffffu, dot, o);
            if (lane == 0) {
                float score = dot * rinvs[r];
                unsigned int u = __float_as_uint(score);
                u = (u & 0x80000000u) ? ~u : (u | 0x80000000u);
                g_key[blockIdx.x * 64 + wid * 4 + r] = u;
            }
        }
    }
    gridbar(1);

    // ===== P4: block 0 — MSB-first radix select, 16 register keys/thread =====
    if (blockIdx.x == 0) {
        unsigned int k[16];
        #pragma unroll
        for (int j = 0; j < 16; ++j) k[j] = g_key[t + NTHR * j];
        if (t == 0) sh_ncand = 0;

        unsigned int prefix = 0;
        int needed = NTOP;
        #pragma unroll
        for (int round = 0; round < 4; ++round) {
            const int shift = 24 - 8 * round;
            if (t < 256) sh.p4.hist[t] = 0;
            __syncthreads();

            #pragma unroll
            for (int j = 0; j < 16; ++j) {
                bool ok = (round == 0) ? true : ((k[j] >> (shift + 8)) == prefix);
                unsigned int active = __ballot_sync(0xffffffffu, ok);
                if (ok) {
                    int bin = (k[j] >> shift) & 0xFF;
                    unsigned int same = __match_any_sync(active, bin);
                    if (lane == __ffs(same) - 1)
                        atomicAdd(&sh.p4.hist[bin], __popc(same));
                }
            }
            __syncthreads();

            if (t < 32) {
                int local[8]; int lsum = 0;
                #pragma unroll
                for (int i = 0; i < 8; ++i) { local[i] = sh.p4.hist[t * 8 + i]; lsum += local[i]; }
                int s = lsum;
                #pragma unroll
                for (int o = 1; o < 32; o <<= 1) {
                    int u = __shfl_up_sync(0xffffffffu, s, o);
                    if (lane >= o) s += u;
                }
                int run = s - lsum;
                #pragma unroll
                for (int i = 0; i < 8; ++i) {
                    if (run < needed && needed <= run + local[i]) {
                        sh_prefix = (prefix << 8) | (unsigned int)(t * 8 + i);
                        sh_needed = needed - run;
                    }
                    run += local[i];
                }
            }
            __syncthreads();
            prefix = sh_prefix;
            needed = sh_needed;
            __syncthreads();
        }
        unsigned int kth = prefix;   // exact 100th-smallest key

        #pragma unroll
        for (int j = 0; j < 16; ++j) {
            if (k[j] <= kth) {
                int p = atomicAdd(&sh_ncand, 1);
                if (p < 256) { sh.p4.ckey[p] = k[j]; sh.p4.cidx[p] = t + NTHR * j; }
            }
        }
        __syncthreads();
        int nc = sh_ncand < 256 ? sh_ncand : 256;

        if (t < nc) {
            unsigned int mk = sh.p4.ckey[t];
            int mi = sh.p4.cidx[t];
            int rank = 0;
            for (int j = 0; j < nc; ++j)
                rank += (sh.p4.ckey[j] < mk ||
                         (sh.p4.ckey[j] == mk && sh.p4.cidx[j] < mi)) ? 1 : 0;
            if (rank < NTOP) {
                g_rank2row[rank] = mi;
                if (NTOP * NDIM + rank < out_size)
                    out[NTOP * NDIM + rank] = (float)mi;
            }
        }
    }
    gridbar(2);

    // ===== P5: blocks 0..99 gather one selected row each =====
    if (blockIdx.x < NTOP && t < ND4) {
        int row = g_rank2row[blockIdx.x];
        int e = blockIdx.x * ND4 + t;
        if (4 * e + 4 <= out_size)
            out4[e] = x4[(size_t)row * ND4 + t];
    }

    // ===== epilogue: last block resets barrier state (post-all-spins) =====
    __syncthreads();
    if (t == 0) {
        __threadfence();
        if (atomicAdd((unsigned int*)&g_bar[3], 1u) == NBLK - 1) {
            g_bar[0] = 0; g_bar[1] = 0; g_bar[2] = 0; g_bar[3] = 0;
            __threadfence();
        }
    }
}

extern "C" void kernel_launch(void* const* d_in, const int* in_sizes, int n_in,
                              void* d_out, int out_size) {
    const float4* x4 = (const float4*)d_in[0];
    kFused<<<NBLK, NTHR>>>(x4, (float*)d_out, (float4*)d_out, out_size);
}